// round 16
// baseline (speedup 1.0000x reference)
#include <cuda_runtime.h>
#include <cuda_bf16.h>
#include <cuda_pipeline.h>
#include <math.h>

#define NB 8
#define NT 1024
#define ND 1024

#define BM 128
#define BN 128
#define KC 64
#define STRIDE 72
#define NCT 8
#define NTILES 36
#define NCHUNK 16
#define STAGEB 36864
#define SMEMB 110592
#define NEGBIG (-1e30f)

__device__ __nv_bfloat16 g_featbf[NB * NT * ND];
__device__ float4 g_stats[NB * NCT * NT];
__device__ float  g_batch[NB];
__device__ int    g_valid[NB];
__device__ int    g_done;

__global__ __launch_bounds__(256) void convert_kernel(const float* __restrict__ feat,
                                                      const int* __restrict__ icl)
{
    if (blockIdx.x == 0) {
        if (threadIdx.x < NB) g_valid[threadIdx.x] = 0;
        if (threadIdx.x == NB) g_done = 0;
    }
    const int brow = blockIdx.x;
    const int bb = brow >> 10;
    const int r = brow & 1023;
    if (r >= icl[bb] + 1) return;
    size_t i = ((size_t)brow * 256 + threadIdx.x) * 4;
    float4 v = *(const float4*)(feat + i);
    __nv_bfloat162 lo = __floats2bfloat162_rn(v.x, v.y);
    __nv_bfloat162 hi = __floats2bfloat162_rn(v.z, v.w);
    *reinterpret_cast<__nv_bfloat162*>(g_featbf + i)     = lo;
    *reinterpret_cast<__nv_bfloat162*>(g_featbf + i + 2) = hi;
}

__device__ __forceinline__ void ldsm4(uint32_t& r0, uint32_t& r1, uint32_t& r2, uint32_t& r3,
                                      const __nv_bfloat16* p)
{
    uint32_t a = (uint32_t)__cvta_generic_to_shared(p);
    asm volatile("ldmatrix.sync.aligned.m8n8.x4.shared.b16 {%0,%1,%2,%3},[%4];"
                 : "=r"(r0), "=r"(r1), "=r"(r2), "=r"(r3) : "r"(a));
}

__device__ __forceinline__ void mma16816(float* c, const uint32_t* a, const uint32_t* b)
{
    asm volatile("mma.sync.aligned.m16n8k16.row.col.f32.bf16.bf16.f32 {%0,%1,%2,%3},{%4,%5,%6,%7},{%8,%9},{%0,%1,%2,%3};"
        : "+f"(c[0]), "+f"(c[1]), "+f"(c[2]), "+f"(c[3])
        : "r"(a[0]), "r"(a[1]), "r"(a[2]), "r"(a[3]), "r"(b[0]), "r"(b[1]));
}

__device__ __forceinline__ void load_tiles(const __nv_bfloat16* fb,
                                           __nv_bfloat16* Ad, __nv_bfloat16* Bd,
                                           int row0, int col0, int k0, int tid)
{
    int s0 = tid;
    int r0r = s0 >> 3;
    int ks0 = (s0 & 7) * 8;
    __pipeline_memcpy_async(Ad + r0r * STRIDE + ks0,
                            fb + (size_t)(row0 + r0r) * ND + k0 + ks0, 16);
    __pipeline_memcpy_async(Bd + r0r * STRIDE + ks0,
                            fb + (size_t)(col0 + r0r) * ND + k0 + ks0, 16);
    int s1 = tid + 512;
    int r1r = s1 >> 3;
    int ks1 = (s1 & 7) * 8;
    __pipeline_memcpy_async(Ad + r1r * STRIDE + ks1,
                            fb + (size_t)(row0 + r1r) * ND + k0 + ks1, 16);
    __pipeline_memcpy_async(Bd + r1r * STRIDE + ks1,
                            fb + (size_t)(col0 + r1r) * ND + k0 + ks1, 16);
    __pipeline_commit();
}

__global__ __launch_bounds__(512, 2) void gemm_kernel(
    const float* __restrict__ masks, const int* __restrict__ icl)
{
    const int b = blockIdx.y;
    int rem = blockIdx.x;
    int rt = 0;
    while (rem >= NCT - rt) { rem -= NCT - rt; rt++; }
    const int ct = rt + rem;

    const int row0 = rt * BM;
    const int col0 = ct * BN;
    const int L    = icl[b] + 1;
    const int tid  = threadIdx.x;

    if (col0 >= L) {
        if (tid < BM) {
            g_stats[(b * NCT + ct) * NT + row0 + tid] = make_float4(NEGBIG, 0.f, 0.f, 0.f);
            if (rt != ct)
                g_stats[(b * NCT + rt) * NT + col0 + tid] = make_float4(NEGBIG, 0.f, 0.f, 0.f);
        }
        return;
    }

    extern __shared__ __align__(16) char dsm[];

    float* s_max = (float*)dsm;
    float* s_sum = s_max + BM * 4;
    float* s_pos = s_sum + BM * 4;
    float* s_cnt = s_pos + BM * 4;
    float* strip = (float*)dsm;

    const int warp = tid >> 5;          // 0..15
    const int lane = tid & 31;
    const int mw = warp >> 2;           // 0..3
    const int nw = warp & 3;            // 0..3
    const __nv_bfloat16* fb = g_featbf + (size_t)b * NT * ND;
    const float* mb = masks + (size_t)b * NT * NT;

    float acc[2][4][4];
    #pragma unroll
    for (int i = 0; i < 2; i++) {
        #pragma unroll
        for (int j = 0; j < 4; j++) {
            acc[i][j][0] = 0.f; acc[i][j][1] = 0.f;
            acc[i][j][2] = 0.f; acc[i][j][3] = 0.f;
        }
    }

    load_tiles(fb, (__nv_bfloat16*)(dsm), (__nv_bfloat16*)(dsm + 18432),
               row0, col0, 0, tid);
    load_tiles(fb, (__nv_bfloat16*)(dsm + STAGEB), (__nv_bfloat16*)(dsm + STAGEB + 18432),
               row0, col0, KC, tid);

    for (int c = 0; c < NCHUNK; c++) {
        if (c + 1 < NCHUNK) {
            __pipeline_wait_prior(1);
        } else {
            __pipeline_wait_prior(0);
        }
        __syncthreads();
        if (c + 2 < NCHUNK) {
            int st2 = (c + 2) % 3;
            load_tiles(fb, (__nv_bfloat16*)(dsm + st2 * STAGEB),
                       (__nv_bfloat16*)(dsm + st2 * STAGEB + 18432),
                       row0, col0, (c + 2) * KC, tid);
        }

        const int stc = c % 3;
        const __nv_bfloat16* Ab = (const __nv_bfloat16*)(dsm + stc * STAGEB);
        const __nv_bfloat16* Bb = (const __nv_bfloat16*)(dsm + stc * STAGEB + 18432);

        #pragma unroll
        for (int kk = 0; kk < KC; kk += 16) {
            uint32_t af[2][4];
            uint32_t bfr[4][2];
            #pragma unroll
            for (int mf = 0; mf < 2; mf++) {
                int r = mw * 32 + mf * 16 + (lane & 15);
                int k = kk + (lane >> 4) * 8;
                ldsm4(af[mf][0], af[mf][1], af[mf][2], af[mf][3], Ab + r * STRIDE + k);
            }
            #pragma unroll
            for (int np = 0; np < 2; np++) {
                int n = nw * 32 + np * 16 + (lane & 7) + ((lane >> 4) << 3);
                int k = kk + (((lane >> 3) & 1) << 3);
                ldsm4(bfr[np * 2][0], bfr[np * 2][1],
                      bfr[np * 2 + 1][0], bfr[np * 2 + 1][1],
                      Bb + n * STRIDE + k);
            }
            #pragma unroll
            for (int mf = 0; mf < 2; mf++) {
                #pragma unroll
                for (int nf = 0; nf < 4; nf++) {
                    mma16816(acc[mf][nf], af[mf], bfr[nf]);
                }
            }
        }
    }
    __syncthreads();

    // ================= epilogue A: rows in rt chunk, cols in ct chunk =================
    const int Lc = min(L - col0, BN);
    int badflag = 0;

    #pragma unroll
    for (int mf = 0; mf < 2; mf++) {
        #pragma unroll
        for (int h = 0; h < 2; h++) {
            const int rloc = mw * 32 + mf * 16 + (lane >> 2) + h * 8;
            const int gi = row0 + rloc;
            const bool rowvalid = (gi < L);
            float vv[4][2];
            float mk[4][2];
            float vmax = NEGBIG;

            #pragma unroll
            for (int nf = 0; nf < 4; nf++) {
                vv[nf][0] = acc[mf][nf][h * 2 + 0] * 10.0f;
                vv[nf][1] = acc[mf][nf][h * 2 + 1] * 10.0f;
                int cc = nw * 32 + nf * 8 + (lane & 3) * 2;
                mk[nf][0] = 0.f;
                mk[nf][1] = 0.f;
                if (rowvalid && cc < Lc) {
                    vmax = fmaxf(vmax, vv[nf][0]);
                    if (cc + 1 < Lc) vmax = fmaxf(vmax, vv[nf][1]);
                    float2 mv = *(const float2*)(mb + (size_t)gi * NT + col0 + cc);
                    mk[nf][0] = mv.x;
                    mk[nf][1] = mv.y;
                }
            }
            vmax = fmaxf(vmax, __shfl_xor_sync(0xffffffffu, vmax, 1));
            vmax = fmaxf(vmax, __shfl_xor_sync(0xffffffffu, vmax, 2));

            float esum = 0.f;
            float psum = 0.f;
            float pcnt = 0.f;
            #pragma unroll
            for (int nf = 0; nf < 4; nf++) {
                #pragma unroll
                for (int j = 0; j < 2; j++) {
                    int cc = nw * 32 + nf * 8 + (lane & 3) * 2 + j;
                    int gj = col0 + cc;
                    if (rowvalid && cc < Lc) {
                        float expect = (gi == gj && gi != 0) ? 1.f : 0.f;
                        if (mk[nf][j] != expect) badflag = 1;
                        if (gj != gi) {
                            esum += __expf(vv[nf][j] - vmax);
                            if (mk[nf][j] != 0.f) {
                                psum += vv[nf][j];
                                pcnt += 1.f;
                            }
                        }
                    }
                }
            }
            esum += __shfl_xor_sync(0xffffffffu, esum, 1);
            esum += __shfl_xor_sync(0xffffffffu, esum, 2);
            psum += __shfl_xor_sync(0xffffffffu, psum, 1);
            psum += __shfl_xor_sync(0xffffffffu, psum, 2);
            pcnt += __shfl_xor_sync(0xffffffffu, pcnt, 1);
            pcnt += __shfl_xor_sync(0xffffffffu, pcnt, 2);

            if ((lane & 3) == 0) {
                s_max[rloc * 4 + nw] = vmax;
                s_sum[rloc * 4 + nw] = esum;
                s_pos[rloc * 4 + nw] = psum;
                s_cnt[rloc * 4 + nw] = pcnt;
            }
        }
    }
    __syncthreads();

    if (tid < BM) {
        float M = NEGBIG;
        float S = 0.f;
        float P = 0.f;
        float C = 0.f;
        #pragma unroll
        for (int w = 0; w < 4; w++) {
            M = fmaxf(M, s_max[tid * 4 + w]);
        }
        #pragma unroll
        for (int w = 0; w < 4; w++) {
            S += s_sum[tid * 4 + w] * __expf(s_max[tid * 4 + w] - M);
            P += s_pos[tid * 4 + w];
            C += s_cnt[tid * 4 + w];
        }
        g_stats[(b * NCT + ct) * NT + row0 + tid] = make_float4(M, S, P, C);
    }

    // ================= epilogue B: rows in ct chunk, cols in rt chunk (transposed) =====
    if (rt != ct) {
        const int Lr = min(L - row0, BM);
        __syncthreads();
        #pragma unroll
        for (int mf = 0; mf < 2; mf++) {
            #pragma unroll
            for (int nf = 0; nf < 4; nf++) {
                #pragma unroll
                for (int e = 0; e < 4; e++) {
                    int row = mw * 32 + mf * 16 + (lane >> 2) + 8 * (e >> 1);
                    int colL = nw * 32 + nf * 8 + (lane & 3) * 2 + (e & 1);
                    strip[colL * 132 + row] = acc[mf][nf][e] * 10.0f;
                }
            }
        }
        __syncthreads();
        #pragma unroll
        for (int cc2 = 0; cc2 < 8; cc2++) {
            int colL = warp * 8 + cc2;
            int gj = col0 + colL;
            bool rowok = (gj < L);
            float v[4];
            float mkv[4];
            const float* mrow = mb + (size_t)gj * NT + row0;
            #pragma unroll
            for (int k = 0; k < 4; k++) {
                int r = lane + 32 * k;
                v[k] = strip[colL * 132 + r];
                mkv[k] = rowok ? mrow[r] : 0.f;
            }
            float vmax = NEGBIG;
            #pragma unroll
            for (int k = 0; k < 4; k++) {
                int r = lane + 32 * k;
                if (rowok && r < Lr) vmax = fmaxf(vmax, v[k]);
            }
            #pragma unroll
            for (int off = 1; off < 32; off <<= 1)
                vmax = fmaxf(vmax, __shfl_xor_sync(0xffffffffu, vmax, off));

            float esum = 0.f;
            float psum = 0.f;
            float pcnt = 0.f;
            #pragma unroll
            for (int k = 0; k < 4; k++) {
                int r = lane + 32 * k;
                if (rowok && r < Lr) {
                    esum += __expf(v[k] - vmax);
                    if (mkv[k] != 0.f) {
                        psum += v[k];
                        pcnt += 1.f;
                        badflag = 1;
                    }
                }
            }
            #pragma unroll
            for (int off = 1; off < 32; off <<= 1) {
                esum += __shfl_xor_sync(0xffffffffu, esum, off);
                psum += __shfl_xor_sync(0xffffffffu, psum, off);
                pcnt += __shfl_xor_sync(0xffffffffu, pcnt, off);
            }
            if (lane == 0) {
                if (rowok)
                    g_stats[(b * NCT + rt) * NT + gj] = make_float4(vmax, esum, psum, pcnt);
                else
                    g_stats[(b * NCT + rt) * NT + gj] = make_float4(NEGBIG, 0.f, 0.f, 0.f);
            }
        }
    }

    if (__syncthreads_or(badflag)) {
        if (tid == 0) atomicOr(&g_valid[b], 1);
    }
}

__global__ __launch_bounds__(1024) void combine_kernel(const int* __restrict__ icl,
                                                       float* __restrict__ out)
{
    const int b = blockIdx.x;
    const int L = icl[b] + 1;
    const int tid = threadIdx.x;
    __shared__ float s_red[1024];

    float local = 0.f;
    const int row = tid;
    if (row < L) {
        float4 st[NCT];
        float M = NEGBIG;
        #pragma unroll
        for (int ctc = 0; ctc < NCT; ctc++) {
            st[ctc] = g_stats[(b * NCT + ctc) * NT + row];
            M = fmaxf(M, st[ctc].x);
        }
        float S = 0.f;
        float P = 0.f;
        float C = 0.f;
        #pragma unroll
        for (int ctc = 0; ctc < NCT; ctc++) {
            S += st[ctc].y * expf(st[ctc].x - M);
            P += st[ctc].z;
            C += st[ctc].w;
        }
        local = (P - C * (M + logf(S + 1e-6f))) / (C + 1e-6f);
    }
    s_red[tid] = local;
    __syncthreads();
    #pragma unroll
    for (int s2 = 512; s2 > 0; s2 >>= 1) {
        if (tid < s2) s_red[tid] += s_red[tid + s2];
        __syncthreads();
    }
    if (tid == 0) {
        g_batch[b] = -s_red[0] / (float)L;
        __threadfence();
        int old = atomicAdd(&g_done, 1);
        if (old == NB - 1) {
            float tot = 0.f;
            float vs = 0.f;
            for (int bi = 0; bi < NB; bi++) {
                tot += g_batch[bi];
                vs += (g_valid[bi] != 0) ? 1.f : 0.f;
            }
            vs = fmaxf(vs, 1.f);
            out[0] = tot / vs;
        }
    }
}

extern "C" void kernel_launch(void* const* d_in, const int* in_sizes, int n_in,
                              void* d_out, int out_size)
{
    const float* feat  = (const float*)d_in[0];
    const float* masks = (const float*)d_in[1];
    const int*   icl   = (const int*)d_in[2];

    cudaFuncSetAttribute(gemm_kernel, cudaFuncAttributeMaxDynamicSharedMemorySize, SMEMB);

    convert_kernel<<<NB * NT, 256>>>(feat, icl);
    dim3 g(NTILES, NB);
    gemm_kernel<<<g, 512, SMEMB>>>(masks, icl);
    combine_kernel<<<NB, 1024>>>(icl, (float*)d_out);
}

// round 17
// speedup vs baseline: 1.0305x; 1.0305x over previous
#include <cuda_runtime.h>
#include <cuda_bf16.h>
#include <cuda_pipeline.h>
#include <math.h>

#define NB 8
#define NT 1024
#define ND 1024

#define BM 128
#define BN 128
#define KC 64
#define STRIDE 72
#define NCT 8
#define NTILES 36
#define NCHUNK 16
#define ASTAGE 18432
#define SMEMB 73728
#define NEGBIG (-1e30f)

__device__ __nv_bfloat16 g_featbf[NB * NT * ND];
__device__ float4 g_stats[NB * NCT * NT];
__device__ float  g_batch[NB];
__device__ int    g_valid[NB];
__device__ int    g_done;
__device__ int    g_tiledone[NB];

__global__ __launch_bounds__(256) void convert_kernel(const float* __restrict__ feat)
{
    if (blockIdx.x == 0) {
        if (threadIdx.x < NB) g_valid[threadIdx.x] = 0;
        if (threadIdx.x >= NB && threadIdx.x < 2 * NB) g_tiledone[threadIdx.x - NB] = 0;
        if (threadIdx.x == 2 * NB) g_done = 0;
    }
    size_t i = ((size_t)blockIdx.x * 256 + threadIdx.x) * 4;
    size_t i2 = i + (size_t)4096 * 1024;
    float4 v = *(const float4*)(feat + i);
    float4 w = *(const float4*)(feat + i2);
    __nv_bfloat162 lo = __floats2bfloat162_rn(v.x, v.y);
    __nv_bfloat162 hi = __floats2bfloat162_rn(v.z, v.w);
    __nv_bfloat162 lo2 = __floats2bfloat162_rn(w.x, w.y);
    __nv_bfloat162 hi2 = __floats2bfloat162_rn(w.z, w.w);
    *reinterpret_cast<__nv_bfloat162*>(g_featbf + i)      = lo;
    *reinterpret_cast<__nv_bfloat162*>(g_featbf + i + 2)  = hi;
    *reinterpret_cast<__nv_bfloat162*>(g_featbf + i2)     = lo2;
    *reinterpret_cast<__nv_bfloat162*>(g_featbf + i2 + 2) = hi2;
}

__device__ __forceinline__ void ldsm4(uint32_t& r0, uint32_t& r1, uint32_t& r2, uint32_t& r3,
                                      const __nv_bfloat16* p)
{
    uint32_t a = (uint32_t)__cvta_generic_to_shared(p);
    asm volatile("ldmatrix.sync.aligned.m8n8.x4.shared.b16 {%0,%1,%2,%3},[%4];"
                 : "=r"(r0), "=r"(r1), "=r"(r2), "=r"(r3) : "r"(a));
}

__device__ __forceinline__ void mma16816(float* c, const uint32_t* a, const uint32_t* b)
{
    asm volatile("mma.sync.aligned.m16n8k16.row.col.f32.bf16.bf16.f32 {%0,%1,%2,%3},{%4,%5,%6,%7},{%8,%9},{%0,%1,%2,%3};"
        : "+f"(c[0]), "+f"(c[1]), "+f"(c[2]), "+f"(c[3])
        : "r"(a[0]), "r"(a[1]), "r"(a[2]), "r"(a[3]), "r"(b[0]), "r"(b[1]));
}

__device__ __forceinline__ void load_tiles(const __nv_bfloat16* fb,
                                           __nv_bfloat16* Ad, __nv_bfloat16* Bd,
                                           int row0, int col0, int k0, int tid)
{
    int s0 = tid;
    int r0r = s0 >> 3;
    int ks0 = (s0 & 7) * 8;
    __pipeline_memcpy_async(Ad + r0r * STRIDE + ks0,
                            fb + (size_t)(row0 + r0r) * ND + k0 + ks0, 16);
    __pipeline_memcpy_async(Bd + r0r * STRIDE + ks0,
                            fb + (size_t)(col0 + r0r) * ND + k0 + ks0, 16);
    int s1 = tid + 512;
    int r1r = s1 >> 3;
    int ks1 = (s1 & 7) * 8;
    __pipeline_memcpy_async(Ad + r1r * STRIDE + ks1,
                            fb + (size_t)(row0 + r1r) * ND + k0 + ks1, 16);
    __pipeline_memcpy_async(Bd + r1r * STRIDE + ks1,
                            fb + (size_t)(col0 + r1r) * ND + k0 + ks1, 16);
    __pipeline_commit();
}

__global__ __launch_bounds__(512, 2) void gemm_kernel(
    const float* __restrict__ masks, const int* __restrict__ icl,
    float* __restrict__ out)
{
    const int b = blockIdx.y;
    int rem = blockIdx.x;
    int rt = 0;
    while (rem >= NCT - rt) { rem -= NCT - rt; rt++; }
    const int ct = rt + rem;

    const int row0 = rt * BM;
    const int col0 = ct * BN;
    const int L    = icl[b] + 1;
    const int tid  = threadIdx.x;

    extern __shared__ __align__(16) char dsm[];
    __shared__ int s_last;

    if (col0 < L) {

    float* s_max = (float*)dsm;
    float* s_sum = s_max + BM * 4;
    float* s_pos = s_sum + BM * 4;
    float* s_cnt = s_pos + BM * 4;
    float* strip = (float*)dsm;

    const int warp = tid >> 5;
    const int lane = tid & 31;
    const int mw = warp >> 2;
    const int nw = warp & 3;
    const __nv_bfloat16* fb = g_featbf + (size_t)b * NT * ND;
    const float* mb = masks + (size_t)b * NT * NT;

    float acc[2][4][4];
    #pragma unroll
    for (int i = 0; i < 2; i++) {
        #pragma unroll
        for (int j = 0; j < 4; j++) {
            acc[i][j][0] = 0.f; acc[i][j][1] = 0.f;
            acc[i][j][2] = 0.f; acc[i][j][3] = 0.f;
        }
    }

    load_tiles(fb, (__nv_bfloat16*)(dsm), (__nv_bfloat16*)(dsm + 2 * ASTAGE),
               row0, col0, 0, tid);

    for (int c = 0; c < NCHUNK; c++) {
        if (c + 1 < NCHUNK) {
            int nbuf = (c + 1) & 1;
            load_tiles(fb, (__nv_bfloat16*)(dsm + nbuf * ASTAGE),
                       (__nv_bfloat16*)(dsm + 2 * ASTAGE + nbuf * ASTAGE),
                       row0, col0, (c + 1) * KC, tid);
            __pipeline_wait_prior(1);
        } else {
            __pipeline_wait_prior(0);
        }
        __syncthreads();

        const __nv_bfloat16* Ab = (const __nv_bfloat16*)(dsm + (c & 1) * ASTAGE);
        const __nv_bfloat16* Bb = (const __nv_bfloat16*)(dsm + 2 * ASTAGE + (c & 1) * ASTAGE);

        #pragma unroll
        for (int kk = 0; kk < KC; kk += 16) {
            uint32_t af[2][4];
            uint32_t bfr[4][2];
            #pragma unroll
            for (int mf = 0; mf < 2; mf++) {
                int r = mw * 32 + mf * 16 + (lane & 15);
                int k = kk + (lane >> 4) * 8;
                ldsm4(af[mf][0], af[mf][1], af[mf][2], af[mf][3], Ab + r * STRIDE + k);
            }
            #pragma unroll
            for (int np = 0; np < 2; np++) {
                int n = nw * 32 + np * 16 + (lane & 7) + ((lane >> 4) << 3);
                int k = kk + (((lane >> 3) & 1) << 3);
                ldsm4(bfr[np * 2][0], bfr[np * 2][1],
                      bfr[np * 2 + 1][0], bfr[np * 2 + 1][1],
                      Bb + n * STRIDE + k);
            }
            #pragma unroll
            for (int mf = 0; mf < 2; mf++) {
                #pragma unroll
                for (int nf = 0; nf < 4; nf++) {
                    mma16816(acc[mf][nf], af[mf], bfr[nf]);
                }
            }
        }
        __syncthreads();
    }

    // ================= epilogue A: rows in rt chunk, cols in ct chunk =================
    const int Lc = min(L - col0, BN);
    int badflag = 0;

    #pragma unroll
    for (int mf = 0; mf < 2; mf++) {
        #pragma unroll
        for (int h = 0; h < 2; h++) {
            const int rloc = mw * 32 + mf * 16 + (lane >> 2) + h * 8;
            const int gi = row0 + rloc;
            const bool rowvalid = (gi < L);
            float vv[4][2];
            float mk[4][2];
            float vmax = NEGBIG;

            #pragma unroll
            for (int nf = 0; nf < 4; nf++) {
                vv[nf][0] = acc[mf][nf][h * 2 + 0] * 10.0f;
                vv[nf][1] = acc[mf][nf][h * 2 + 1] * 10.0f;
                int cc = nw * 32 + nf * 8 + (lane & 3) * 2;
                mk[nf][0] = 0.f;
                mk[nf][1] = 0.f;
                if (rowvalid && cc < Lc) {
                    vmax = fmaxf(vmax, vv[nf][0]);
                    if (cc + 1 < Lc) vmax = fmaxf(vmax, vv[nf][1]);
                    float2 mv = *(const float2*)(mb + (size_t)gi * NT + col0 + cc);
                    mk[nf][0] = mv.x;
                    mk[nf][1] = mv.y;
                }
            }
            vmax = fmaxf(vmax, __shfl_xor_sync(0xffffffffu, vmax, 1));
            vmax = fmaxf(vmax, __shfl_xor_sync(0xffffffffu, vmax, 2));

            float esum = 0.f;
            float psum = 0.f;
            float pcnt = 0.f;
            #pragma unroll
            for (int nf = 0; nf < 4; nf++) {
                #pragma unroll
                for (int j = 0; j < 2; j++) {
                    int cc = nw * 32 + nf * 8 + (lane & 3) * 2 + j;
                    int gj = col0 + cc;
                    if (rowvalid && cc < Lc) {
                        float expect = (gi == gj && gi != 0) ? 1.f : 0.f;
                        if (mk[nf][j] != expect) badflag = 1;
                        if (gj != gi) {
                            esum += __expf(vv[nf][j] - vmax);
                            if (mk[nf][j] != 0.f) {
                                psum += vv[nf][j];
                                pcnt += 1.f;
                            }
                        }
                    }
                }
            }
            esum += __shfl_xor_sync(0xffffffffu, esum, 1);
            esum += __shfl_xor_sync(0xffffffffu, esum, 2);
            psum += __shfl_xor_sync(0xffffffffu, psum, 1);
            psum += __shfl_xor_sync(0xffffffffu, psum, 2);
            pcnt += __shfl_xor_sync(0xffffffffu, pcnt, 1);
            pcnt += __shfl_xor_sync(0xffffffffu, pcnt, 2);

            if ((lane & 3) == 0) {
                s_max[rloc * 4 + nw] = vmax;
                s_sum[rloc * 4 + nw] = esum;
                s_pos[rloc * 4 + nw] = psum;
                s_cnt[rloc * 4 + nw] = pcnt;
            }
        }
    }
    __syncthreads();

    if (tid < BM) {
        float M = NEGBIG;
        float S = 0.f;
        float P = 0.f;
        float C = 0.f;
        #pragma unroll
        for (int w = 0; w < 4; w++) {
            M = fmaxf(M, s_max[tid * 4 + w]);
        }
        #pragma unroll
        for (int w = 0; w < 4; w++) {
            S += s_sum[tid * 4 + w] * __expf(s_max[tid * 4 + w] - M);
            P += s_pos[tid * 4 + w];
            C += s_cnt[tid * 4 + w];
        }
        g_stats[(b * NCT + ct) * NT + row0 + tid] = make_float4(M, S, P, C);
    }

    // ================= epilogue B: rows in ct chunk, cols in rt chunk (transposed) =====
    if (rt != ct) {
        const int Lr = min(L - row0, BM);
        __syncthreads();
        #pragma unroll
        for (int mf = 0; mf < 2; mf++) {
            #pragma unroll
            for (int nf = 0; nf < 4; nf++) {
                #pragma unroll
                for (int e = 0; e < 4; e++) {
                    int row = mw * 32 + mf * 16 + (lane >> 2) + 8 * (e >> 1);
                    int colL = nw * 32 + nf * 8 + (lane & 3) * 2 + (e & 1);
                    strip[colL * 132 + row] = acc[mf][nf][e] * 10.0f;
                }
            }
        }
        __syncthreads();
        #pragma unroll
        for (int cc2 = 0; cc2 < 8; cc2++) {
            int colL = warp * 8 + cc2;
            int gj = col0 + colL;
            bool rowok = (gj < L);
            float v[4];
            float mkv[4];
            const float* mrow = mb + (size_t)gj * NT + row0;
            #pragma unroll
            for (int k = 0; k < 4; k++) {
                int r = lane + 32 * k;
                v[k] = strip[colL * 132 + r];
                mkv[k] = rowok ? mrow[r] : 0.f;
            }
            float vmax = NEGBIG;
            #pragma unroll
            for (int k = 0; k < 4; k++) {
                int r = lane + 32 * k;
                if (rowok && r < Lr) vmax = fmaxf(vmax, v[k]);
            }
            #pragma unroll
            for (int off = 1; off < 32; off <<= 1)
                vmax = fmaxf(vmax, __shfl_xor_sync(0xffffffffu, vmax, off));

            float esum = 0.f;
            float psum = 0.f;
            float pcnt = 0.f;
            #pragma unroll
            for (int k = 0; k < 4; k++) {
                int r = lane + 32 * k;
                if (rowok && r < Lr) {
                    esum += __expf(v[k] - vmax);
                    if (mkv[k] != 0.f) {
                        psum += v[k];
                        pcnt += 1.f;
                        badflag = 1;
                    }
                }
            }
            #pragma unroll
            for (int off = 1; off < 32; off <<= 1) {
                esum += __shfl_xor_sync(0xffffffffu, esum, off);
                psum += __shfl_xor_sync(0xffffffffu, psum, off);
                pcnt += __shfl_xor_sync(0xffffffffu, pcnt, off);
            }
            if (lane == 0 && rowok) {
                g_stats[(b * NCT + rt) * NT + gj] = make_float4(vmax, esum, psum, pcnt);
            }
        }
    }

    if (__syncthreads_or(badflag)) {
        if (tid == 0) atomicOr(&g_valid[b], 1);
    }
    __syncthreads();

    }   // end if (col0 < L)

    // ============== common tail: count tiles; last block of batch combines ==============
    if (tid == 0) {
        __threadfence();
        int old = atomicAdd(&g_tiledone[b], 1);
        s_last = (old == NTILES - 1) ? 1 : 0;
    }
    __syncthreads();
    if (s_last != 0) {
        __threadfence();
        const int nbt2 = (L + 127) >> 7;
        float* s_red = (float*)dsm;
        float local = 0.f;
        for (int row = tid; row < NT; row += 512) {
            if (row < L) {
                float M = NEGBIG;
                float S = 0.f;
                float P = 0.f;
                float C = 0.f;
                for (int j = 0; j < nbt2; j++) {
                    float4 st = g_stats[(b * NCT + j) * NT + row];
                    float nm = fmaxf(M, st.x);
                    S = S * __expf(M - nm) + st.y * __expf(st.x - nm);
                    M = nm;
                    P += st.z;
                    C += st.w;
                }
                local += (P - C * (M + logf(S + 1e-6f))) / (C + 1e-6f);
            }
        }
        s_red[tid] = local;
        __syncthreads();
        #pragma unroll
        for (int s2 = 256; s2 > 0; s2 >>= 1) {
            if (tid < s2) s_red[tid] += s_red[tid + s2];
            __syncthreads();
        }
        if (tid == 0) {
            g_batch[b] = -s_red[0] / (float)L;
            __threadfence();
            int old2 = atomicAdd(&g_done, 1);
            if (old2 == NB - 1) {
                __threadfence();
                float tot = 0.f;
                float vs = 0.f;
                for (int bi = 0; bi < NB; bi++) {
                    tot += g_batch[bi];
                    vs += (g_valid[bi] != 0) ? 1.f : 0.f;
                }
                vs = fmaxf(vs, 1.f);
                out[0] = tot / vs;
            }
        }
    }
}

extern "C" void kernel_launch(void* const* d_in, const int* in_sizes, int n_in,
                              void* d_out, int out_size)
{
    const float* feat  = (const float*)d_in[0];
    const float* masks = (const float*)d_in[1];
    const int*   icl   = (const int*)d_in[2];

    cudaFuncSetAttribute(gemm_kernel, cudaFuncAttributeMaxDynamicSharedMemorySize, SMEMB);

    convert_kernel<<<4096, 256>>>(feat);
    dim3 g(NTILES, NB);
    gemm_kernel<<<g, 512, SMEMB>>>(masks, icl, (float*)d_out);
}